// round 8
// baseline (speedup 1.0000x reference)
#include <cuda_runtime.h>
#include <cstdint>

#define NTHR   256
#define HCTA   32
#define TOPKN  512
#define KCH    128
#define SCALE_F 0.041666666666666664f
#define NEGINF __int_as_float(0xff800000)

#define N4 4718592   // (32768*576)/4 == (512*64*576)/4

__device__ __align__(16) uint2 g_kvh[N4];
__device__ __align__(16) uint2 g_kvl[N4];
__device__ __align__(16) uint2 g_qh[N4];
__device__ __align__(16) uint2 g_ql[N4];

// ---- smem byte offsets (per 32-head CTA) ----
#define OFF_IDX   0        // 512*4
#define OFF_M     2048     // 32*4
#define OFF_L     2176
#define OFF_C     2304
#define OFF_WMAX  2432     // 4*32*4
#define OFF_WSUM  2944     // ends 3456
#define KH_(i)    (3584 + (i)*36864)   // K slice 128x144B hi; lo +18432 (ends 77312)
#define QH_(i)    (77312 + (i)*9216)   // Q slice 32x144B hi; lo +4608 (ends 95744)
#define VH_(i)    (3584 + (i)*33280)   // V tile 16x1040B hi; lo +16640 (overlay K, ends 70144)
#define OFF_PH    95744                // P 32x272B; lo +8704
#define SMEM_TOTAL 113152

__device__ __forceinline__ uint32_t smem_u32(const void* p) {
    uint32_t a;
    asm("{ .reg .u64 t; cvta.to.shared.u64 t, %1; cvt.u32.u64 %0, t; }" : "=r"(a) : "l"(p));
    return a;
}
__device__ __forceinline__ void split2(float x, float y, uint32_t& h2, uint32_t& l2) {
    uint32_t ux = __float_as_uint(x), uy = __float_as_uint(y);
    h2 = __byte_perm(ux, uy, 0x7632);
    float xl = x - __uint_as_float(ux & 0xffff0000u);
    float yl = y - __uint_as_float(uy & 0xffff0000u);
    asm("cvt.rn.bf16x2.f32 %0, %1, %2;" : "=r"(l2) : "f"(yl), "f"(xl));
}
__device__ __forceinline__ void ldsm4(uint32_t* r, uint32_t a) {
    asm volatile("ldmatrix.sync.aligned.m8n8.x4.shared.b16 {%0,%1,%2,%3}, [%4];"
                 : "=r"(r[0]), "=r"(r[1]), "=r"(r[2]), "=r"(r[3]) : "r"(a));
}
__device__ __forceinline__ void ldsm4t(uint32_t* r, uint32_t a) {
    asm volatile("ldmatrix.sync.aligned.m8n8.x4.trans.shared.b16 {%0,%1,%2,%3}, [%4];"
                 : "=r"(r[0]), "=r"(r[1]), "=r"(r[2]), "=r"(r[3]) : "r"(a));
}
__device__ __forceinline__ void mma16(float* d, const uint32_t* a, uint32_t b0, uint32_t b1) {
    asm volatile(
        "mma.sync.aligned.m16n8k16.row.col.f32.bf16.bf16.f32 "
        "{%0,%1,%2,%3}, {%4,%5,%6,%7}, {%8,%9}, {%0,%1,%2,%3};"
        : "+f"(d[0]), "+f"(d[1]), "+f"(d[2]), "+f"(d[3])
        : "r"(a[0]), "r"(a[1]), "r"(a[2]), "r"(a[3]), "r"(b0), "r"(b1));
}
__device__ __forceinline__ void cpa(uint32_t dst, const void* src, uint32_t sz) {
    asm volatile("cp.async.cg.shared.global [%0], [%1], 16, %2;"
                 :: "r"(dst), "l"(src), "r"(sz) : "memory");
}
#define CP_COMMIT() asm volatile("cp.async.commit_group;" ::: "memory")
#define CP_WAIT(n)  asm volatile("cp.async.wait_group %0;" :: "n"(n) : "memory")

// ================= preprocessing: fp32 -> bf16 hi/lo =================
__global__ __launch_bounds__(256)
void conv_kernel(const float* __restrict__ kv, const float* __restrict__ qq)
{
    uint32_t i = blockIdx.x * 256u + threadIdx.x;
    const float* src;
    uint2 *dh, *dl;
    uint32_t o;
    if (i < N4) {
        o = i; src = kv + (size_t)o * 4; dh = g_kvh; dl = g_kvl;
    } else {
        o = i - N4; src = qq + (size_t)o * 4; dh = g_qh; dl = g_ql;
    }
    float4 v = *reinterpret_cast<const float4*>(src);
    uint32_t h0, l0, h1, l1;
    split2(v.x, v.y, h0, l0);
    split2(v.z, v.w, h1, l1);
    dh[o] = make_uint2(h0, h1);
    dl[o] = make_uint2(l0, l1);
}

// ================= gather issue helpers (256 threads) =================
__device__ __forceinline__ void issue_kq(uint32_t smb, const int* idx_s,
                                         int ci, int ds, int t, int hbase, int tid, int bi)
{
    {   // K slice [128 keys x 64 d]: 2 threads/row, 64B hi + 64B lo each
        int row = tid >> 1, sub = tid & 1;
        int gi = idx_s[ci * KCH + row];
        uint32_t sz = gi >= 0 ? 16u : 0u;
        size_t rb = (size_t)(gi >= 0 ? gi : 0) * 1152 + (size_t)ds * 128 + sub * 64;
        const char* sh = (const char*)g_kvh + rb;
        const char* sl = (const char*)g_kvl + rb;
        uint32_t d = smb + KH_(bi) + row * 144 + sub * 64;
        #pragma unroll
        for (int j = 0; j < 4; ++j) {
            cpa(d + j * 16,         sh + j * 16, sz);
            cpa(d + 18432 + j * 16, sl + j * 16, sz);
        }
    }
    {   // Q slice [32 heads x 64 d]: 8 threads/row
        int row = tid >> 3, sub = tid & 7;
        size_t rb = ((size_t)t * 64 + hbase + row) * 1152 + (size_t)ds * 128 + sub * 16;
        uint32_t d = smb + QH_(bi) + row * 144 + sub * 16;
        cpa(d,        (const char*)g_qh + rb, 16);
        cpa(d + 4608, (const char*)g_ql + rb, 16);
    }
}
__device__ __forceinline__ void issue_v(uint32_t smb, const int* idx_s,
                                        int ci, int kst, int tid, int bi)
{
    // V tile [16 keys x 512 dv]: 16 threads/row, 64B hi + 64B lo each
    int row = tid >> 4, sub = tid & 15;
    int gi = idx_s[ci * KCH + kst * 16 + row];
    uint32_t sz = gi >= 0 ? 16u : 0u;
    size_t rb = (size_t)(gi >= 0 ? gi : 0) * 1152 + sub * 64;
    const char* sh = (const char*)g_kvh + rb;
    const char* sl = (const char*)g_kvl + rb;
    uint32_t d = smb + VH_(bi) + row * 1040 + sub * 64;
    #pragma unroll
    for (int j = 0; j < 4; ++j) {
        cpa(d + j * 16,         sh + j * 16, sz);
        cpa(d + 16640 + j * 16, sl + j * 16, sz);
    }
}

// ================= main attention kernel =================
__global__ __launch_bounds__(NTHR, 2)
void mla_mma_kernel(const int* __restrict__ topk,
                    const float* __restrict__ sink,
                    float* __restrict__ out)
{
    extern __shared__ char sm[];
    const uint32_t smb = smem_u32(sm);
    const int tid = threadIdx.x;
    const int w = tid >> 5, l = tid & 31;
    const int hg = w >> 2;          // 0..1 (16 heads each)
    const int kg = w & 3;           // QK: key group of 32; PV: dv group of 128
    const int t = blockIdx.y;
    const int hbase = blockIdx.x * HCTA;

    int*   idx_s  = reinterpret_cast<int*>(sm + OFF_IDX);
    float* m_s    = reinterpret_cast<float*>(sm + OFF_M);
    float* l_s    = reinterpret_cast<float*>(sm + OFF_L);
    float* c_s    = reinterpret_cast<float*>(sm + OFF_C);
    float* wmax_s = reinterpret_cast<float*>(sm + OFF_WMAX);
    float* wsum_s = reinterpret_cast<float*>(sm + OFF_WSUM);

    idx_s[tid]       = __ldg(topk + (size_t)t * TOPKN + tid);
    idx_s[tid + 256] = __ldg(topk + (size_t)t * TOPKN + tid + 256);
    if (tid < HCTA) { m_s[tid] = __ldg(sink + hbase + tid); l_s[tid] = 1.f; }
    __syncthreads();

    float o[16][4];
    #pragma unroll
    for (int i = 0; i < 16; ++i)
        #pragma unroll
        for (int j = 0; j < 4; ++j) o[i][j] = 0.f;

    for (int ci = 0; ci < 4; ++ci) {
        float sacc[4][4];
        #pragma unroll
        for (int i = 0; i < 4; ++i)
            #pragma unroll
            for (int j = 0; j < 4; ++j) sacc[i][j] = 0.f;

        // ============ QK over 9 d-slices, double-buffered cp.async ============
        issue_kq(smb, idx_s, ci, 0, t, hbase, tid, 0);
        CP_COMMIT();
        for (int ds = 0; ds < 9; ++ds) {
            if (ds < 8) {
                issue_kq(smb, idx_s, ci, ds + 1, t, hbase, tid, (ds + 1) & 1);
                CP_COMMIT();
                CP_WAIT(1);
            } else {
                CP_WAIT(0);
            }
            __syncthreads();
            const int bi = ds & 1;
            #pragma unroll
            for (int ks = 0; ks < 4; ++ks) {
                uint32_t qh[4], ql[4], kh[8], kl[8];
                uint32_t qa = smb + QH_(bi) + (hg * 16 + (l & 15)) * 144 + (ks * 16 + (l >> 4) * 8) * 2;
                ldsm4(qh, qa);
                ldsm4(ql, qa + 4608);
                uint32_t ka = smb + KH_(bi) + (kg * 32 + (l & 15)) * 144 + (ks * 16 + (l >> 4) * 8) * 2;
                ldsm4(kh, ka);
                ldsm4(kh + 4, ka + 16 * 144);
                ldsm4(kl, ka + 18432);
                ldsm4(kl + 4, ka + 18432 + 16 * 144);
                mma16(sacc[0], qh, kh[0], kh[2]); mma16(sacc[0], qh, kl[0], kl[2]); mma16(sacc[0], ql, kh[0], kh[2]);
                mma16(sacc[1], qh, kh[1], kh[3]); mma16(sacc[1], qh, kl[1], kl[3]); mma16(sacc[1], ql, kh[1], kh[3]);
                mma16(sacc[2], qh, kh[4], kh[6]); mma16(sacc[2], qh, kl[4], kl[6]); mma16(sacc[2], ql, kh[4], kh[6]);
                mma16(sacc[3], qh, kh[5], kh[7]); mma16(sacc[3], qh, kl[5], kl[7]); mma16(sacc[3], ql, kh[5], kh[7]);
            }
            __syncthreads();
        }

        // prefetch first two V tiles (independent of softmax)
        issue_v(smb, idx_s, ci, 0, tid, 0);
        CP_COMMIT();
        issue_v(smb, idx_s, ci, 1, tid, 1);
        CP_COMMIT();

        // ============ online softmax (register fragments) ============
        float rm0 = NEGINF, rm1 = NEGINF;
        #pragma unroll
        for (int nt = 0; nt < 4; ++nt) {
            int kb = ci * KCH + kg * 32 + nt * 8 + (l & 3) * 2;
            bool v0 = idx_s[kb] >= 0, v1 = idx_s[kb + 1] >= 0;
            float s0 = v0 ? sacc[nt][0] * SCALE_F : NEGINF;
            float s1 = v1 ? sacc[nt][1] * SCALE_F : NEGINF;
            float s2 = v0 ? sacc[nt][2] * SCALE_F : NEGINF;
            float s3 = v1 ? sacc[nt][3] * SCALE_F : NEGINF;
            sacc[nt][0] = s0; sacc[nt][1] = s1; sacc[nt][2] = s2; sacc[nt][3] = s3;
            rm0 = fmaxf(rm0, fmaxf(s0, s1));
            rm1 = fmaxf(rm1, fmaxf(s2, s3));
        }
        rm0 = fmaxf(rm0, __shfl_xor_sync(0xffffffffu, rm0, 1));
        rm0 = fmaxf(rm0, __shfl_xor_sync(0xffffffffu, rm0, 2));
        rm1 = fmaxf(rm1, __shfl_xor_sync(0xffffffffu, rm1, 1));
        rm1 = fmaxf(rm1, __shfl_xor_sync(0xffffffffu, rm1, 2));
        if ((l & 3) == 0) {
            wmax_s[kg * 32 + hg * 16 + (l >> 2)]     = rm0;
            wmax_s[kg * 32 + hg * 16 + 8 + (l >> 2)] = rm1;
        }
        __syncthreads();
        if (tid < HCTA) {
            float mo = m_s[tid];
            float mn = mo;
            #pragma unroll
            for (int g = 0; g < 4; ++g) mn = fmaxf(mn, wmax_s[g * 32 + tid]);
            float cr = __expf(mo - mn);
            m_s[tid] = mn; c_s[tid] = cr; l_s[tid] *= cr;
        }
        __syncthreads();
        float mr0 = m_s[hg * 16 + (l >> 2)];
        float mr1 = m_s[hg * 16 + 8 + (l >> 2)];
        float sum0 = 0.f, sum1 = 0.f;
        #pragma unroll
        for (int nt = 0; nt < 4; ++nt) {
            float e0 = __expf(sacc[nt][0] - mr0);
            float e1 = __expf(sacc[nt][1] - mr0);
            float e2 = __expf(sacc[nt][2] - mr1);
            float e3 = __expf(sacc[nt][3] - mr1);
            sum0 += e0 + e1; sum1 += e2 + e3;
            uint32_t ha, la, hb, lb;
            split2(e0, e1, ha, la);
            split2(e2, e3, hb, lb);
            uint32_t col = (uint32_t)(kg * 32 + nt * 8 + (l & 3) * 2) * 2;
            uint32_t r0o = (uint32_t)(hg * 16 + (l >> 2)) * 272 + col;
            uint32_t r1o = r0o + 8 * 272;
            *reinterpret_cast<uint32_t*>(sm + OFF_PH + r0o)        = ha;
            *reinterpret_cast<uint32_t*>(sm + OFF_PH + 8704 + r0o) = la;
            *reinterpret_cast<uint32_t*>(sm + OFF_PH + r1o)        = hb;
            *reinterpret_cast<uint32_t*>(sm + OFF_PH + 8704 + r1o) = lb;
        }
        sum0 += __shfl_xor_sync(0xffffffffu, sum0, 1);
        sum0 += __shfl_xor_sync(0xffffffffu, sum0, 2);
        sum1 += __shfl_xor_sync(0xffffffffu, sum1, 1);
        sum1 += __shfl_xor_sync(0xffffffffu, sum1, 2);
        if ((l & 3) == 0) {
            wsum_s[kg * 32 + hg * 16 + (l >> 2)]     = sum0;
            wsum_s[kg * 32 + hg * 16 + 8 + (l >> 2)] = sum1;
        }
        __syncthreads();
        if (tid < HCTA)
            l_s[tid] += wsum_s[tid] + wsum_s[32 + tid] + wsum_s[64 + tid] + wsum_s[96 + tid];
        float c0 = c_s[hg * 16 + (l >> 2)];
        float c1 = c_s[hg * 16 + 8 + (l >> 2)];
        #pragma unroll
        for (int nt = 0; nt < 16; ++nt) {
            o[nt][0] *= c0; o[nt][1] *= c0; o[nt][2] *= c1; o[nt][3] *= c1;
        }

        // ============ PV over 8 key-steps of 16, double-buffered ============
        for (int kst = 0; kst < 8; ++kst) {
            if (kst < 7) CP_WAIT(1); else CP_WAIT(0);
            __syncthreads();
            const int bi = kst & 1;
            uint32_t ph[4], pl[4];
            uint32_t pa = smb + OFF_PH + (hg * 16 + (l & 15)) * 272 +
                          (kst * 16 + (l >> 4) * 8) * 2;
            ldsm4(ph, pa);
            ldsm4(pl, pa + 8704);
            #pragma unroll
            for (int dvt = 0; dvt < 8; ++dvt) {
                uint32_t vh[4], vl[4];
                uint32_t va = smb + VH_(bi) + (l & 15) * 1040 +
                              (kg * 128 + dvt * 16 + (l >> 4) * 8) * 2;
                ldsm4t(vh, va);
                ldsm4t(vl, va + 16640);
                float* o0 = o[dvt * 2];
                float* o1 = o[dvt * 2 + 1];
                mma16(o0, ph, vh[0], vh[1]); mma16(o0, ph, vl[0], vl[1]); mma16(o0, pl, vh[0], vh[1]);
                mma16(o1, ph, vh[2], vh[3]); mma16(o1, ph, vl[2], vl[3]); mma16(o1, pl, vh[2], vh[3]);
            }
            __syncthreads();
            if (kst + 2 <= 7) {
                issue_v(smb, idx_s, ci, kst + 2, tid, kst & 1);
                CP_COMMIT();
            }
        }
    }

    // ============ epilogue ============
    float n0 = 1.f / l_s[hg * 16 + (l >> 2)];
    float n1 = 1.f / l_s[hg * 16 + 8 + (l >> 2)];
    float* ob0 = out + ((size_t)t * 64 + hbase + hg * 16 + (l >> 2)) * 512;
    float* ob1 = ob0 + 8 * 512;
    #pragma unroll
    for (int nt = 0; nt < 16; ++nt) {
        int dv = kg * 128 + nt * 8 + (l & 3) * 2;
        *reinterpret_cast<float2*>(ob0 + dv) = make_float2(o[nt][0] * n0, o[nt][1] * n0);
        *reinterpret_cast<float2*>(ob1 + dv) = make_float2(o[nt][2] * n1, o[nt][3] * n1);
    }
}

extern "C" void kernel_launch(void* const* d_in, const int* in_sizes, int n_in,
                              void* d_out, int out_size)
{
    const float* q    = (const float*)d_in[0];
    const float* kv   = (const float*)d_in[1];
    const int*   topk = (const int*)d_in[2];
    const float* sink = (const float*)d_in[3];
    float* out = (float*)d_out;

    conv_kernel<<<(2 * N4) / 256, 256>>>(kv, q);

    cudaFuncSetAttribute(mla_mma_kernel, cudaFuncAttributeMaxDynamicSharedMemorySize, SMEM_TOTAL);
    dim3 grid(2, 512);
    mla_mma_kernel<<<grid, NTHR, SMEM_TOTAL>>>(topk, sink, out);
}

// round 9
// speedup vs baseline: 1.2388x; 1.2388x over previous
#include <cuda_runtime.h>
#include <cstdint>

#define NTHR   512
#define HEADS  64
#define TOPKN  512
#define KCH    128
#define SCALE_F 0.041666666666666664f
#define NEGINF __int_as_float(0xff800000)

#define N4 4718592   // (32768*576)/4 == (512*64*576)/4

__device__ __align__(16) uint2 g_kvh[N4];
__device__ __align__(16) uint2 g_kvl[N4];
__device__ __align__(16) uint2 g_qh[N4];
__device__ __align__(16) uint2 g_ql[N4];

// ---- smem byte offsets ----
#define OFF_IDX   0
#define OFF_M     2048
#define OFF_L     2304
#define OFF_C     2560
#define OFF_WMAX  2816
#define OFF_WSUM  3840
#define OFF_PH    5120                 // P: 64 rows * 272B; lo at +17408 (ends 39936)
#define OFF_PL    22528
#define KH_(s)    (39936 + (s)*36864)  // K slice: 128x144B hi; lo +18432 (3 stages, ends 150528)
#define QH_(s)    (150528 + (s)*18432) // Q slice: 64x144B hi; lo +9216 (3 stages, ends 205824)
#define VH_(i)    (39936 + (i)*66560)  // V tile: 32x1040B hi; lo +33280 (overlay K/Q, ends 173056)
#define SMEM_TOTAL 205824

__device__ __forceinline__ uint32_t smem_u32(const void* p) {
    uint32_t a;
    asm("{ .reg .u64 t; cvta.to.shared.u64 t, %1; cvt.u32.u64 %0, t; }" : "=r"(a) : "l"(p));
    return a;
}
__device__ __forceinline__ void split2(float x, float y, uint32_t& h2, uint32_t& l2) {
    uint32_t ux = __float_as_uint(x), uy = __float_as_uint(y);
    h2 = __byte_perm(ux, uy, 0x7632);
    float xl = x - __uint_as_float(ux & 0xffff0000u);
    float yl = y - __uint_as_float(uy & 0xffff0000u);
    asm("cvt.rn.bf16x2.f32 %0, %1, %2;" : "=r"(l2) : "f"(yl), "f"(xl));
}
__device__ __forceinline__ void ldsm4(uint32_t* r, uint32_t a) {
    asm volatile("ldmatrix.sync.aligned.m8n8.x4.shared.b16 {%0,%1,%2,%3}, [%4];"
                 : "=r"(r[0]), "=r"(r[1]), "=r"(r[2]), "=r"(r[3]) : "r"(a));
}
__device__ __forceinline__ void ldsm4t(uint32_t* r, uint32_t a) {
    asm volatile("ldmatrix.sync.aligned.m8n8.x4.trans.shared.b16 {%0,%1,%2,%3}, [%4];"
                 : "=r"(r[0]), "=r"(r[1]), "=r"(r[2]), "=r"(r[3]) : "r"(a));
}
__device__ __forceinline__ void mma16(float* d, const uint32_t* a, uint32_t b0, uint32_t b1) {
    asm volatile(
        "mma.sync.aligned.m16n8k16.row.col.f32.bf16.bf16.f32 "
        "{%0,%1,%2,%3}, {%4,%5,%6,%7}, {%8,%9}, {%0,%1,%2,%3};"
        : "+f"(d[0]), "+f"(d[1]), "+f"(d[2]), "+f"(d[3])
        : "r"(a[0]), "r"(a[1]), "r"(a[2]), "r"(a[3]), "r"(b0), "r"(b1));
}
__device__ __forceinline__ void cpa(uint32_t dst, const void* src, uint32_t sz) {
    asm volatile("cp.async.cg.shared.global [%0], [%1], 16, %2;"
                 :: "r"(dst), "l"(src), "r"(sz) : "memory");
}
#define CP_COMMIT() asm volatile("cp.async.commit_group;" ::: "memory")
#define CP_WAIT(n)  asm volatile("cp.async.wait_group %0;" :: "n"(n) : "memory")

// ================= preprocessing: fp32 -> bf16 hi/lo =================
__global__ __launch_bounds__(256)
void conv_kernel(const float* __restrict__ kv, const float* __restrict__ qq)
{
    uint32_t i = blockIdx.x * 256u + threadIdx.x;
    const float* src;
    uint2 *dh, *dl;
    uint32_t o;
    if (i < N4) {
        o = i; src = kv + (size_t)o * 4; dh = g_kvh; dl = g_kvl;
    } else {
        o = i - N4; src = qq + (size_t)o * 4; dh = g_qh; dl = g_ql;
    }
    float4 v = *reinterpret_cast<const float4*>(src);
    uint32_t h0, l0, h1, l1;
    split2(v.x, v.y, h0, l0);
    split2(v.z, v.w, h1, l1);
    dh[o] = make_uint2(h0, h1);
    dl[o] = make_uint2(l0, l1);
}

// ================= gather issue helpers =================
__device__ __forceinline__ void issue_kq(uint32_t smb, const int* idx_s,
                                         int ci, int ds, int t, int tid, int st)
{
    {   // K slice [128 keys x 64 d]: 4 threads/row
        int row = tid >> 2, sub = tid & 3;
        int gi = idx_s[ci * KCH + row];
        uint32_t sz = gi >= 0 ? 16u : 0u;
        size_t rb = (size_t)(gi >= 0 ? gi : 0) * 1152 + (size_t)ds * 128 + sub * 32;
        const char* sh = (const char*)g_kvh + rb;
        const char* sl = (const char*)g_kvl + rb;
        uint32_t d = smb + KH_(st) + row * 144 + sub * 32;
        cpa(d,              sh,      sz);
        cpa(d + 16,         sh + 16, sz);
        cpa(d + 18432,      sl,      sz);
        cpa(d + 18432 + 16, sl + 16, sz);
    }
    {   // Q slice [64 heads x 64 d]: 8 threads/row
        int row = tid >> 3, sub = tid & 7;
        size_t rb = ((size_t)t * 64 + row) * 1152 + (size_t)ds * 128 + sub * 16;
        uint32_t d = smb + QH_(st) + row * 144 + sub * 16;
        cpa(d,        (const char*)g_qh + rb, 16);
        cpa(d + 9216, (const char*)g_ql + rb, 16);
    }
}
__device__ __forceinline__ void issue_v(uint32_t smb, const int* idx_s,
                                        int ci, int kst, int tid, int bi)
{
    // V tile [32 keys x 512 dv]: 16 threads/row
    int row = tid >> 4, sub = tid & 15;
    int gi = idx_s[ci * KCH + kst * 32 + row];
    uint32_t sz = gi >= 0 ? 16u : 0u;
    size_t rb = (size_t)(gi >= 0 ? gi : 0) * 1152 + sub * 64;
    const char* sh = (const char*)g_kvh + rb;
    const char* sl = (const char*)g_kvl + rb;
    uint32_t d = smb + VH_(bi) + row * 1040 + sub * 64;
    #pragma unroll
    for (int j = 0; j < 4; ++j) {
        cpa(d + j * 16,         sh + j * 16, sz);
        cpa(d + 33280 + j * 16, sl + j * 16, sz);
    }
}

// ================= main attention kernel =================
__global__ __launch_bounds__(NTHR, 1)
void mla_mma_kernel(const int* __restrict__ topk,
                    const float* __restrict__ sink,
                    float* __restrict__ out)
{
    extern __shared__ char sm[];
    const uint32_t smb = smem_u32(sm);
    const int tid = threadIdx.x;
    const int w = tid >> 5, l = tid & 31;
    const int hg = w >> 2;
    const int kg = w & 3;
    const int t = blockIdx.x;

    int*   idx_s  = reinterpret_cast<int*>(sm + OFF_IDX);
    float* m_s    = reinterpret_cast<float*>(sm + OFF_M);
    float* l_s    = reinterpret_cast<float*>(sm + OFF_L);
    float* c_s    = reinterpret_cast<float*>(sm + OFF_C);
    float* wmax_s = reinterpret_cast<float*>(sm + OFF_WMAX);
    float* wsum_s = reinterpret_cast<float*>(sm + OFF_WSUM);

    idx_s[tid] = __ldg(topk + (size_t)t * TOPKN + tid);
    if (tid < HEADS) { m_s[tid] = __ldg(sink + tid); l_s[tid] = 1.f; }
    __syncthreads();

    float o[16][4];
    #pragma unroll
    for (int i = 0; i < 16; ++i)
        #pragma unroll
        for (int j = 0; j < 4; ++j) o[i][j] = 0.f;

    for (int ci = 0; ci < 4; ++ci) {
        float sacc[4][4];
        #pragma unroll
        for (int i = 0; i < 4; ++i)
            #pragma unroll
            for (int j = 0; j < 4; ++j) sacc[i][j] = 0.f;

        // ===== QK over 9 d-slices: 3-stage pipeline, one sync per slice =====
        issue_kq(smb, idx_s, ci, 0, t, tid, 0);
        CP_COMMIT();
        issue_kq(smb, idx_s, ci, 1, t, tid, 1);
        CP_COMMIT();
        for (int ds = 0; ds < 9; ++ds) {
            if (ds < 8) CP_WAIT(1); else CP_WAIT(0);
            __syncthreads();   // ds data visible + all warps done with stage (ds-1)%3
            if (ds < 7) {
                issue_kq(smb, idx_s, ci, ds + 2, t, tid, (ds + 2) % 3);
                CP_COMMIT();
            }
            if (ds == 8) {     // V tile 0 overlays stages 0/1 only; stage 2 in use
                issue_v(smb, idx_s, ci, 0, tid, 0);
                CP_COMMIT();
            }
            const int st = ds % 3;
            #pragma unroll
            for (int ks = 0; ks < 4; ++ks) {
                uint32_t qh[4], ql[4], kh[8], kl[8];
                uint32_t qa = smb + QH_(st) + (hg * 16 + (l & 15)) * 144 + (ks * 16 + (l >> 4) * 8) * 2;
                ldsm4(qh, qa);
                ldsm4(ql, qa + 9216);
                uint32_t ka = smb + KH_(st) + (kg * 32 + (l & 15)) * 144 + (ks * 16 + (l >> 4) * 8) * 2;
                ldsm4(kh, ka);
                ldsm4(kh + 4, ka + 16 * 144);
                ldsm4(kl, ka + 18432);
                ldsm4(kl + 4, ka + 18432 + 16 * 144);
                mma16(sacc[0], qh, kh[0], kh[2]); mma16(sacc[0], qh, kl[0], kl[2]); mma16(sacc[0], ql, kh[0], kh[2]);
                mma16(sacc[1], qh, kh[1], kh[3]); mma16(sacc[1], qh, kl[1], kl[3]); mma16(sacc[1], ql, kh[1], kh[3]);
                mma16(sacc[2], qh, kh[4], kh[6]); mma16(sacc[2], qh, kl[4], kl[6]); mma16(sacc[2], ql, kh[4], kh[6]);
                mma16(sacc[3], qh, kh[5], kh[7]); mma16(sacc[3], qh, kl[5], kl[7]); mma16(sacc[3], ql, kh[5], kh[7]);
            }
        }

        // ============ online softmax (register fragments) ============
        float rm0 = NEGINF, rm1 = NEGINF;
        #pragma unroll
        for (int nt = 0; nt < 4; ++nt) {
            int kb = ci * KCH + kg * 32 + nt * 8 + (l & 3) * 2;
            bool v0 = idx_s[kb] >= 0, v1 = idx_s[kb + 1] >= 0;
            float s0 = v0 ? sacc[nt][0] * SCALE_F : NEGINF;
            float s1 = v1 ? sacc[nt][1] * SCALE_F : NEGINF;
            float s2 = v0 ? sacc[nt][2] * SCALE_F : NEGINF;
            float s3 = v1 ? sacc[nt][3] * SCALE_F : NEGINF;
            sacc[nt][0] = s0; sacc[nt][1] = s1; sacc[nt][2] = s2; sacc[nt][3] = s3;
            rm0 = fmaxf(rm0, fmaxf(s0, s1));
            rm1 = fmaxf(rm1, fmaxf(s2, s3));
        }
        rm0 = fmaxf(rm0, __shfl_xor_sync(0xffffffffu, rm0, 1));
        rm0 = fmaxf(rm0, __shfl_xor_sync(0xffffffffu, rm0, 2));
        rm1 = fmaxf(rm1, __shfl_xor_sync(0xffffffffu, rm1, 1));
        rm1 = fmaxf(rm1, __shfl_xor_sync(0xffffffffu, rm1, 2));
        if ((l & 3) == 0) {
            wmax_s[kg * 64 + hg * 16 + (l >> 2)]     = rm0;
            wmax_s[kg * 64 + hg * 16 + 8 + (l >> 2)] = rm1;
        }
        __syncthreads();   // also: all warps done reading K stage 2 -> V tile 1 may overwrite
        issue_v(smb, idx_s, ci, 1, tid, 1);
        CP_COMMIT();
        if (tid < HEADS) {
            float mo = m_s[tid];
            float mn = mo;
            #pragma unroll
            for (int g = 0; g < 4; ++g) mn = fmaxf(mn, wmax_s[g * 64 + tid]);
            float cr = __expf(mo - mn);
            m_s[tid] = mn; c_s[tid] = cr; l_s[tid] *= cr;
        }
        __syncthreads();
        float mr0 = m_s[hg * 16 + (l >> 2)];
        float mr1 = m_s[hg * 16 + 8 + (l >> 2)];
        float sum0 = 0.f, sum1 = 0.f;
        #pragma unroll
        for (int nt = 0; nt < 4; ++nt) {
            float e0 = __expf(sacc[nt][0] - mr0);
            float e1 = __expf(sacc[nt][1] - mr0);
            float e2 = __expf(sacc[nt][2] - mr1);
            float e3 = __expf(sacc[nt][3] - mr1);
            sum0 += e0 + e1; sum1 += e2 + e3;
            uint32_t ha, la, hb, lb;
            split2(e0, e1, ha, la);
            split2(e2, e3, hb, lb);
            uint32_t col = (uint32_t)(kg * 32 + nt * 8 + (l & 3) * 2) * 2;
            uint32_t r0o = (uint32_t)(hg * 16 + (l >> 2)) * 272 + col;
            uint32_t r1o = r0o + 8 * 272;
            *reinterpret_cast<uint32_t*>(sm + OFF_PH + r0o) = ha;
            *reinterpret_cast<uint32_t*>(sm + OFF_PL + r0o) = la;
            *reinterpret_cast<uint32_t*>(sm + OFF_PH + r1o) = hb;
            *reinterpret_cast<uint32_t*>(sm + OFF_PL + r1o) = lb;
        }
        sum0 += __shfl_xor_sync(0xffffffffu, sum0, 1);
        sum0 += __shfl_xor_sync(0xffffffffu, sum0, 2);
        sum1 += __shfl_xor_sync(0xffffffffu, sum1, 1);
        sum1 += __shfl_xor_sync(0xffffffffu, sum1, 2);
        if ((l & 3) == 0) {
            wsum_s[kg * 64 + hg * 16 + (l >> 2)]     = sum0;
            wsum_s[kg * 64 + hg * 16 + 8 + (l >> 2)] = sum1;
        }
        __syncthreads();
        if (tid < HEADS)
            l_s[tid] += wsum_s[tid] + wsum_s[64 + tid] + wsum_s[128 + tid] + wsum_s[192 + tid];
        float c0 = c_s[hg * 16 + (l >> 2)];
        float c1 = c_s[hg * 16 + 8 + (l >> 2)];
        #pragma unroll
        for (int nt = 0; nt < 16; ++nt) {
            o[nt][0] *= c0; o[nt][1] *= c0; o[nt][2] *= c1; o[nt][3] *= c1;
        }

        // ============ PV over 4 key-steps, double-buffered ============
        for (int kst = 0; kst < 4; ++kst) {
            if (kst < 3) CP_WAIT(1); else CP_WAIT(0);
            __syncthreads();
            const int bi = kst & 1;
            #pragma unroll
            for (int kk = 0; kk < 2; ++kk) {
                uint32_t ph[4], pl[4];
                uint32_t pa = smb + OFF_PH + (hg * 16 + (l & 15)) * 272 +
                              (kst * 32 + kk * 16 + (l >> 4) * 8) * 2;
                ldsm4(ph, pa);
                ldsm4(pl, pa + 17408);
                #pragma unroll
                for (int dvt = 0; dvt < 8; ++dvt) {
                    uint32_t vh[4], vl[4];
                    uint32_t va = smb + VH_(bi) + (kk * 16 + (l & 15)) * 1040 +
                                  (kg * 128 + dvt * 16 + (l >> 4) * 8) * 2;
                    ldsm4t(vh, va);
                    ldsm4t(vl, va + 33280);
                    float* o0 = o[dvt * 2];
                    float* o1 = o[dvt * 2 + 1];
                    mma16(o0, ph, vh[0], vh[1]); mma16(o0, ph, vl[0], vl[1]); mma16(o0, pl, vh[0], vh[1]);
                    mma16(o1, ph, vh[2], vh[3]); mma16(o1, ph, vl[2], vl[3]); mma16(o1, pl, vh[2], vh[3]);
                }
            }
            __syncthreads();
            if (kst + 2 <= 3) {
                issue_v(smb, idx_s, ci, kst + 2, tid, kst & 1);
                CP_COMMIT();
            }
        }
    }

    // ============ epilogue ============
    float n0 = 1.f / l_s[hg * 16 + (l >> 2)];
    float n1 = 1.f / l_s[hg * 16 + 8 + (l >> 2)];
    float* ob0 = out + ((size_t)t * HEADS + hg * 16 + (l >> 2)) * 512;
    float* ob1 = ob0 + 8 * 512;
    #pragma unroll
    for (int nt = 0; nt < 16; ++nt) {
        int dv = kg * 128 + nt * 8 + (l & 3) * 2;
        *reinterpret_cast<float2*>(ob0 + dv) = make_float2(o[nt][0] * n0, o[nt][1] * n0);
        *reinterpret_cast<float2*>(ob1 + dv) = make_float2(o[nt][2] * n1, o[nt][3] * n1);
    }
}

extern "C" void kernel_launch(void* const* d_in, const int* in_sizes, int n_in,
                              void* d_out, int out_size)
{
    const float* q    = (const float*)d_in[0];
    const float* kv   = (const float*)d_in[1];
    const int*   topk = (const int*)d_in[2];
    const float* sink = (const float*)d_in[3];
    float* out = (float*)d_out;

    conv_kernel<<<(2 * N4) / 256, 256>>>(kv, q);

    cudaFuncSetAttribute(mla_mma_kernel, cudaFuncAttributeMaxDynamicSharedMemorySize, SMEM_TOTAL);
    mla_mma_kernel<<<512, NTHR, SMEM_TOTAL>>>(topk, sink, out);
}